// round 9
// baseline (speedup 1.0000x reference)
#include <cuda_runtime.h>
#include <cuda_fp16.h>
#include <math.h>
#include <cstdint>

// ===========================================================================
// Fused MLP, all GEMMs on HMMA fp16 single-product:
//   prep_x : x fp32 -> fp16 [B,384]; row-stats proj -> g_statproj[B,32] fp16
//   prep_w : W1/W2/W3/Wc1 -> transposed fp16
//   gemm<1>: h1 = relu(x@W1+b1)    [B,512] fp16   (K-chunk 128)
//   gemm<2>: h2 = relu(h1@W2+b2)   [B,256] fp16   (K-chunk 128)
//   tail   : fused gemm3 (h2@W3 -> smem comb) + C1 HMMA + C2/C3 + sigmoid
// ===========================================================================

#define MTOT 65536

// ---------------- device scratch -------------------------------------------
__device__ __half g_x[(size_t)MTOT * 384];
__device__ __half g_w1[512 * 384];
__device__ __half g_w2[256 * 512];
__device__ __half g_w3[128 * 256];
__device__ __half g_wc1t[64 * 160];
__device__ __half g_h1[(size_t)MTOT * 512];
__device__ __half g_h2[(size_t)MTOT * 256];
__device__ __half g_statproj[(size_t)MTOT * 32];

// ---------------- helpers --------------------------------------------------
__device__ __forceinline__ uint32_t smem_to_u32(const void* p) {
    uint32_t a;
    asm("{ .reg .u64 t; cvta.to.shared.u64 t, %1; cvt.u32.u64 %0, t; }"
        : "=r"(a) : "l"(p));
    return a;
}
__device__ __forceinline__ void ldsm4(uint32_t* r, uint32_t addr) {
    asm volatile("ldmatrix.sync.aligned.m8n8.x4.shared.b16 {%0,%1,%2,%3}, [%4];"
        : "=r"(r[0]), "=r"(r[1]), "=r"(r[2]), "=r"(r[3]) : "r"(addr));
}
__device__ __forceinline__ void mma16816(float* c, const uint32_t* a,
                                         const uint32_t* b) {
    asm volatile(
        "mma.sync.aligned.m16n8k16.row.col.f32.f16.f16.f32 "
        "{%0,%1,%2,%3}, {%4,%5,%6,%7}, {%8,%9}, {%0,%1,%2,%3};"
        : "+f"(c[0]), "+f"(c[1]), "+f"(c[2]), "+f"(c[3])
        : "r"(a[0]), "r"(a[1]), "r"(a[2]), "r"(a[3]), "r"(b[0]), "r"(b[1]));
}
__device__ __forceinline__ void cp_async16(uint32_t dst, const void* src) {
    asm volatile("cp.async.cg.shared.global [%0], [%1], 16;"
        :: "r"(dst), "l"(src));
}
#define CP_COMMIT() asm volatile("cp.async.commit_group;" ::: "memory")
#define CP_WAIT(n)  asm volatile("cp.async.wait_group %0;" :: "n"(n) : "memory")

__device__ __forceinline__ uint32_t pack_h2(__half a, __half b) {
    __half2 t; t.x = a; t.y = b;
    return *(uint32_t*)&t;
}

// ---------------- prep_x ----------------------------------------------------
__global__ __launch_bounds__(256)
void prep_x_kernel(const float* __restrict__ x,
                   const float* __restrict__ Ws, const float* __restrict__ bs) {
    const int warp = threadIdx.x >> 5, lane = threadIdx.x & 31;
    const int r = blockIdx.x * 8 + warp;
    const float* xr = x + (size_t)r * 365;

    float v[12];
    float s = 0.f, mn = 3.4e38f, mx = -3.4e38f;
#pragma unroll
    for (int i = 0; i < 12; i++) {
        int k = lane + 32 * i;
        bool ok = k < 365;
        v[i] = ok ? xr[k] : 0.f;
        if (ok) { s += v[i]; mn = fminf(mn, v[i]); mx = fmaxf(mx, v[i]); }
    }
#pragma unroll
    for (int o = 16; o; o >>= 1) {
        s += __shfl_xor_sync(0xffffffffu, s, o);
        mn = fminf(mn, __shfl_xor_sync(0xffffffffu, mn, o));
        mx = fmaxf(mx, __shfl_xor_sync(0xffffffffu, mx, o));
    }
    const float mu = s * (1.0f / 365.0f);
    float s2 = 0.f, s3 = 0.f, s4 = 0.f;
#pragma unroll
    for (int i = 0; i < 12; i++) {
        int k = lane + 32 * i;
        if (k < 365) {
            float c = v[i] - mu, c2 = c * c;
            s2 += c2; s3 += c2 * c; s4 += c2 * c2;
        }
    }
#pragma unroll
    for (int o = 16; o; o >>= 1) {
        s2 += __shfl_xor_sync(0xffffffffu, s2, o);
        s3 += __shfl_xor_sync(0xffffffffu, s3, o);
        s4 += __shfl_xor_sync(0xffffffffu, s4, o);
    }
    const float var1 = s2 * (1.0f / 364.0f);
    const float sig = sqrtf(var1);
    const float m3 = s3 * (1.0f / 365.0f);
    const float m4 = s4 * (1.0f / 365.0f);
    const float sig2 = sig * sig;
    const float skew = m3 / (sig * sig2 + 1e-8f);
    const float kurt = m4 / (sig2 * sig2 + 1e-8f);

    {   // stats projection: lane j computes output col j
        const int j = lane;
        float a = bs[j];
        a += mu   * Ws[0 * 32 + j];
        a += sig  * Ws[1 * 32 + j];
        a += mn   * Ws[2 * 32 + j];
        a += mx   * Ws[3 * 32 + j];
        a += skew * Ws[4 * 32 + j];
        a += kurt * Ws[5 * 32 + j];
        g_statproj[(size_t)r * 32 + j] = __float2half_rn(a);
    }
#pragma unroll
    for (int i = 0; i < 12; i++) {
        int k = lane + 32 * i;
        float val = (k < 365) ? v[i] : 0.f;
        g_x[(size_t)r * 384 + k] = __float2half_rn(val);
    }
}

// ---------------- prep_w ----------------------------------------------------
#define W1T_ELEMS (512 * 384)
#define W2T_ELEMS (256 * 512)
#define W3T_ELEMS (128 * 256)
#define WC1T_ELEMS (64 * 160)
#define WT_TOTAL  (W1T_ELEMS + W2T_ELEMS + W3T_ELEMS + WC1T_ELEMS)

__global__ __launch_bounds__(256)
void prep_w_kernel(const float* __restrict__ W1, const float* __restrict__ W2,
                   const float* __restrict__ W3, const float* __restrict__ Wc1) {
    int idx = blockIdx.x * 256 + threadIdx.x;
    if (idx >= WT_TOTAL) return;
    if (idx < W1T_ELEMS) {
        int n = idx / 384, k = idx % 384;
        float v = (k < 365) ? W1[(size_t)k * 512 + n] : 0.f;
        g_w1[idx] = __float2half_rn(v);
    } else if (idx < W1T_ELEMS + W2T_ELEMS) {
        int j = idx - W1T_ELEMS;
        int n = j / 512, k = j % 512;
        g_w2[j] = __float2half_rn(W2[(size_t)k * 256 + n]);
    } else if (idx < W1T_ELEMS + W2T_ELEMS + W3T_ELEMS) {
        int j = idx - W1T_ELEMS - W2T_ELEMS;
        int n = j / 256, k = j % 256;
        g_w3[j] = __float2half_rn(W3[(size_t)k * 128 + n]);
    } else {
        int j = idx - W1T_ELEMS - W2T_ELEMS - W3T_ELEMS;
        int n = j / 160, k = j % 160;
        g_wc1t[j] = __float2half_rn(Wc1[(size_t)k * 64 + n]);
    }
}

// ---------------- HMMA GEMM layers 1/2: K-chunk 128, 2-stage cp.async ------
template <int LAYER>
__global__ __launch_bounds__(512, 1)
void gemm_hmma_kernel(const float* __restrict__ bias) {
    constexpr int KPAD  = (LAYER == 1) ? 384 : 512;
    constexpr int BLK_N = 256;
    constexpr int OUTLD = (LAYER == 1) ? 512 : 256;
    constexpr int KB    = KPAD / 128;
    constexpr int LDSB  = 272;                // 128 fp16 + 16B pad
    constexpr int WARP_N = 64;
    constexpr int NWT    = 4;
    constexpr int NT     = 8;

    constexpr uint32_t A_S  = 0;
    constexpr uint32_t B_S  = 128 * LDSB;                 // 34816
    constexpr uint32_t SBUF = B_S + BLK_N * LDSB;         // 104448

    const __half* A_g = (LAYER == 1) ? g_x  : g_h1;
    const __half* B_g = (LAYER == 1) ? g_w1 : g_w2;
    __half* O = (LAYER == 1) ? g_h1 : g_h2;

    extern __shared__ char smem[];
    const uint32_t sb = smem_to_u32(smem);

    const int tid = threadIdx.x, warp = tid >> 5, lane = tid & 31;
    const int row0 = blockIdx.x * 128;
    const int nbase = blockIdx.y * BLK_N;
    const int wm = (warp & 3) * 32;
    const int wn = (warp >> 2) * WARP_N;

    float acc[2][NT][4];
#pragma unroll
    for (int mt = 0; mt < 2; mt++)
#pragma unroll
        for (int t = 0; t < NT; t++)
#pragma unroll
            for (int j = 0; j < 4; j++) acc[mt][t][j] = 0.f;

    const uint32_t a_off = (uint32_t)(wm + (lane & 15)) * LDSB + ((lane >> 4) * 16);
    const uint32_t b_off = (uint32_t)(wn + (lane & 7) + ((lane >> 4) << 3)) * LDSB
                           + (((lane >> 3) & 1) * 16);

    // one 128-K chunk: A = 2048 granules (16B), B = 4096 granules
    auto load_chunk = [&](int kb, int buf) {
        const uint32_t bb = sb + (uint32_t)buf * SBUF;
        const size_t abase = (size_t)row0 * KPAD + kb * 128;
#pragma unroll
        for (int it = 0; it < 4; it++) {
            const int idx = tid + it * 512;
            const int r = idx >> 4, g = idx & 15;
            const size_t src = abase + (size_t)r * KPAD + g * 8;
            cp_async16(bb + A_S + r * LDSB + g * 16, A_g + src);
        }
        const size_t bbase = (size_t)nbase * KPAD + kb * 128;
#pragma unroll
        for (int it = 0; it < 8; it++) {
            const int idx = tid + it * 512;
            const int n = idx >> 4, g = idx & 15;
            const size_t src = bbase + (size_t)n * KPAD + g * 8;
            cp_async16(bb + B_S + n * LDSB + g * 16, B_g + src);
        }
    };

    load_chunk(0, 0);
    CP_COMMIT();

    for (int kb = 0; kb < KB; kb++) {
        __syncthreads();
        if (kb + 1 < KB) {
            load_chunk(kb + 1, (kb + 1) & 1);
            CP_COMMIT();
            CP_WAIT(1);
        } else {
            CP_WAIT(0);
        }
        __syncthreads();

        const uint32_t bb = sb + (uint32_t)(kb & 1) * SBUF;
#pragma unroll
        for (int ks = 0; ks < 8; ks++) {
            uint32_t ah[2][4];
#pragma unroll
            for (int mt = 0; mt < 2; mt++)
                ldsm4(ah[mt], bb + A_S + a_off + mt * (16 * LDSB) + ks * 32);
#pragma unroll
            for (int t = 0; t < NWT; t++) {
                uint32_t bh[4];
                ldsm4(bh, bb + B_S + b_off + t * (16 * LDSB) + ks * 32);
#pragma unroll
                for (int mt = 0; mt < 2; mt++) {
                    mma16816(acc[mt][2 * t],     ah[mt], bh);
                    mma16816(acc[mt][2 * t + 1], ah[mt], bh + 2);
                }
            }
        }
    }

    // ---- epilogue: bias + relu -> fp16 ----
#pragma unroll
    for (int mt = 0; mt < 2; mt++) {
        const int r0 = row0 + wm + mt * 16 + (lane >> 2);
        const int r1 = r0 + 8;
#pragma unroll
        for (int t = 0; t < NT; t++) {
            const int ncol = wn + t * 8 + (lane & 3) * 2;
            const float b0 = bias[nbase + ncol];
            const float b1 = bias[nbase + ncol + 1];
            float d0 = fmaxf(acc[mt][t][0] + b0, 0.f);
            float d1 = fmaxf(acc[mt][t][1] + b1, 0.f);
            float d2 = fmaxf(acc[mt][t][2] + b0, 0.f);
            float d3 = fmaxf(acc[mt][t][3] + b1, 0.f);
            *(uint32_t*)(O + (size_t)r0 * OUTLD + nbase + ncol) =
                pack_h2(__float2half_rn(d0), __float2half_rn(d1));
            *(uint32_t*)(O + (size_t)r1 * OUTLD + nbase + ncol) =
                pack_h2(__float2half_rn(d2), __float2half_rn(d3));
        }
    }
}

// ---------------- fused tail: gemm3 (to smem) + C1 HMMA + C2/C3 ------------
// 512 thr, M-tile 128. gemm3: K=256 (4 chunks of 64), N=128 -> smem comb.
// head C1: comb[128,160] @ Wc1T -> c1s; C2/C3 fp32 in smem.
__global__ __launch_bounds__(512, 1)
void tail_kernel(const float* __restrict__ b3,
                 const float* __restrict__ bc1,
                 const float* __restrict__ Wc2, const float* __restrict__ bc2,
                 const float* __restrict__ Wc3, const float* __restrict__ bc3,
                 float* __restrict__ out) {
    // pipeline region (K-chunk 64, LDSB=144)
    constexpr int LDSB = 144;
    constexpr uint32_t A_S  = 0;
    constexpr uint32_t B_S  = 128 * LDSB;               // 18432
    constexpr uint32_t SBUF = B_S + 128 * LDSB;         // 36864 (x2 = 73728)
    // head regions
    constexpr int LDH = 336;                             // 160 fp16 + pad
    constexpr uint32_t COMB = 73728;                     // 128 x 336 = 43008
    constexpr uint32_t WC1  = COMB + 43008;              // 64 x 336 = 21504
    constexpr uint32_t C1S  = WC1 + 21504;               // 128 x 65 fp32 = 33280
    constexpr uint32_t WC2S = C1S + 33280;               // 8192
    constexpr uint32_t WC3S = WC2S + 8192;               // 128
    // total 179840

    extern __shared__ char smem[];
    const uint32_t sb = smem_to_u32(smem);
    float* smf = (float*)smem;

    const int tid = threadIdx.x, warp = tid >> 5, lane = tid & 31;
    const int row0 = blockIdx.x * 128;
    const int wm = (warp & 3) * 32;

    // ---- prologue: head constants + stats cols + gemm3 chunk 0 ----
    for (int i = tid; i < 1280; i += 512) {            // Wc1T: 64 x 20 gran
        int r = i / 20, g = i % 20;
        cp_async16(sb + WC1 + r * LDH + g * 16, g_wc1t + r * 160 + g * 8);
    }
    {                                                   // statproj -> comb[:,128:160]
        const int r = tid >> 2, g = tid & 3;            // wait: 512 thr = 512 gran? need 128*4=512 ✓
        cp_async16(sb + COMB + r * LDH + 256 + g * 16,
                   g_statproj + (size_t)(row0 + r) * 32 + g * 8);
    }
    for (int i = tid; i < 512; i += 512)                // Wc2: 2048 floats
        cp_async16(sb + WC2S + i * 16, Wc2 + i * 4);
    if (tid < 8)
        cp_async16(sb + WC3S + tid * 16, Wc3 + tid * 4);

    // gemm3 chunk loader (K-chunk 64): A (h2) 1024 gran, B (w3) 1024 gran
    auto load_chunk = [&](int kb, int buf) {
        const uint32_t bb = sb + (uint32_t)buf * SBUF;
        const size_t abase = (size_t)row0 * 256 + kb * 64;
#pragma unroll
        for (int it = 0; it < 2; it++) {
            const int idx = tid + it * 512;
            const int r = idx >> 3, g = idx & 7;
            cp_async16(bb + A_S + r * LDSB + g * 16,
                       g_h2 + abase + (size_t)r * 256 + g * 8);
        }
        const size_t bbase = (size_t)kb * 64;
#pragma unroll
        for (int it = 0; it < 2; it++) {
            const int idx = tid + it * 512;
            const int n = idx >> 3, g = idx & 7;
            cp_async16(bb + B_S + n * LDSB + g * 16,
                       g_w3 + bbase + (size_t)n * 256 + g * 8);
        }
    };
    load_chunk(0, 0);
    CP_COMMIT();

    // ---- gemm3 mainloop: BLK_N=128, WARP_N=32, NWT=2 ----
    const int wn3 = (warp >> 2) * 32;
    float acc[2][4][4];
#pragma unroll
    for (int mt = 0; mt < 2; mt++)
#pragma unroll
        for (int t = 0; t < 4; t++)
#pragma unroll
            for (int j = 0; j < 4; j++) acc[mt][t][j] = 0.f;

    const uint32_t a_off = (uint32_t)(wm + (lane & 15)) * LDSB + ((lane >> 4) * 16);
    const uint32_t b_off3 = (uint32_t)(wn3 + (lane & 7) + ((lane >> 4) << 3)) * LDSB
                            + (((lane >> 3) & 1) * 16);

    for (int kb = 0; kb < 4; kb++) {
        __syncthreads();
        if (kb + 1 < 4) {
            load_chunk(kb + 1, (kb + 1) & 1);
            CP_COMMIT();
            CP_WAIT(1);
        } else {
            CP_WAIT(0);
        }
        __syncthreads();

        const uint32_t bb = sb + (uint32_t)(kb & 1) * SBUF;
#pragma unroll
        for (int ks = 0; ks < 4; ks++) {
            uint32_t ah[2][4];
#pragma unroll
            for (int mt = 0; mt < 2; mt++)
                ldsm4(ah[mt], bb + A_S + a_off + mt * (16 * LDSB) + ks * 32);
#pragma unroll
            for (int t = 0; t < 2; t++) {
                uint32_t bh[4];
                ldsm4(bh, bb + B_S + b_off3 + t * (16 * LDSB) + ks * 32);
#pragma unroll
                for (int mt = 0; mt < 2; mt++) {
                    mma16816(acc[mt][2 * t],     ah[mt], bh);
                    mma16816(acc[mt][2 * t + 1], ah[mt], bh + 2);
                }
            }
        }
    }

    // gemm3 epilogue: bias+relu -> smem comb cols [0,128)
    __half* combh = (__half*)(smem + COMB);
#pragma unroll
    for (int mt = 0; mt < 2; mt++) {
        const int r0 = wm + mt * 16 + (lane >> 2);
        const int r1 = r0 + 8;
#pragma unroll
        for (int t = 0; t < 4; t++) {
            const int ncol = wn3 + t * 8 + (lane & 3) * 2;
            const float b0 = b3[ncol], b1 = b3[ncol + 1];
            float d0 = fmaxf(acc[mt][t][0] + b0, 0.f);
            float d1 = fmaxf(acc[mt][t][1] + b1, 0.f);
            float d2 = fmaxf(acc[mt][t][2] + b0, 0.f);
            float d3 = fmaxf(acc[mt][t][3] + b1, 0.f);
            *(uint32_t*)((char*)combh + r0 * LDH + ncol * 2) =
                pack_h2(__float2half_rn(d0), __float2half_rn(d1));
            *(uint32_t*)((char*)combh + r1 * LDH + ncol * 2) =
                pack_h2(__float2half_rn(d2), __float2half_rn(d3));
        }
    }
    __syncthreads();

    // ---- C1: HMMA comb[128,160] @ Wc1T[64,160]; warp grid 4m x 4n ----
    const int wnh = (warp >> 2) * 16;
    float acch[2][2][4];
#pragma unroll
    for (int mt = 0; mt < 2; mt++)
#pragma unroll
        for (int t = 0; t < 2; t++)
#pragma unroll
            for (int j = 0; j < 4; j++) acch[mt][t][j] = 0.f;

    const uint32_t a_offh = (uint32_t)(wm + (lane & 15)) * LDH + ((lane >> 4) * 16);
    const uint32_t b_offh = (uint32_t)(wnh + (lane & 7) + ((lane >> 4) << 3)) * LDH
                            + (((lane >> 3) & 1) * 16);
#pragma unroll
    for (int ks = 0; ks < 10; ks++) {
        uint32_t ah[2][4];
#pragma unroll
        for (int mt = 0; mt < 2; mt++)
            ldsm4(ah[mt], sb + COMB + a_offh + mt * (16 * LDH) + ks * 32);
        uint32_t bh[4];
        ldsm4(bh, sb + WC1 + b_offh + ks * 32);
#pragma unroll
        for (int mt = 0; mt < 2; mt++) {
            mma16816(acch[mt][0], ah[mt], bh);
            mma16816(acch[mt][1], ah[mt], bh + 2);
        }
    }
    // C1 epilogue -> c1s (stride 65 fp32)
    float* c1s = smf + C1S / 4;
#pragma unroll
    for (int mt = 0; mt < 2; mt++) {
        const int r0 = wm + mt * 16 + (lane >> 2);
        const int r1 = r0 + 8;
#pragma unroll
        for (int t = 0; t < 2; t++) {
            const int ncol = wnh + t * 8 + (lane & 3) * 2;
            const float b0 = bc1[ncol], b1 = bc1[ncol + 1];
            c1s[r0 * 65 + ncol]     = fmaxf(acch[mt][t][0] + b0, 0.f);
            c1s[r0 * 65 + ncol + 1] = fmaxf(acch[mt][t][1] + b1, 0.f);
            c1s[r1 * 65 + ncol]     = fmaxf(acch[mt][t][2] + b0, 0.f);
            c1s[r1 * 65 + ncol + 1] = fmaxf(acch[mt][t][3] + b1, 0.f);
        }
    }
    __syncthreads();

    // ---- C2: [128,64]@[64,32]; thread r=tid>>2, 8 cols ----
    float* wc2s = smf + WC2S / 4;
    float* c2s  = smf + COMB / 4;            // reuse comb region, stride 33
    {
        const int r = tid >> 2;
        const int j0 = (tid & 3) * 8;
        float a[8];
#pragma unroll
        for (int j = 0; j < 8; j++) a[j] = bc2[j0 + j];
        const float* c1r = c1s + r * 65;
        for (int k = 0; k < 64; k++) {
            const float v = c1r[k];
            const float* w = wc2s + k * 32 + j0;
#pragma unroll
            for (int j = 0; j < 8; j++) a[j] += v * w[j];
        }
        float* c2r = c2s + r * 33;
#pragma unroll
        for (int j = 0; j < 8; j++) c2r[j0 + j] = fmaxf(a[j], 0.f);
    }
    __syncthreads();

    // ---- C3 + sigmoid ----
    if (tid < 128) {
        const float* c2r = c2s + tid * 33;
        const float* w3 = smf + WC3S / 4;
        float z = bc3[0];
#pragma unroll
        for (int k = 0; k < 32; k++) z += c2r[k] * w3[k];
        out[row0 + tid] = 1.0f / (1.0f + expf(-z));
    }
}

// ---------------- launch ---------------------------------------------------
extern "C" void kernel_launch(void* const* d_in, const int* in_sizes, int n_in,
                              void* d_out, int out_size) {
    const float* x   = (const float*)d_in[0];
    const float* W1  = (const float*)d_in[1];
    const float* b1  = (const float*)d_in[2];
    const float* W2  = (const float*)d_in[3];
    const float* b2  = (const float*)d_in[4];
    const float* W3  = (const float*)d_in[5];
    const float* b3  = (const float*)d_in[6];
    const float* Ws  = (const float*)d_in[7];
    const float* bs  = (const float*)d_in[8];
    const float* Wc1 = (const float*)d_in[9];
    const float* bc1 = (const float*)d_in[10];
    const float* Wc2 = (const float*)d_in[11];
    const float* bc2 = (const float*)d_in[12];
    const float* Wc3 = (const float*)d_in[13];
    const float* bc3 = (const float*)d_in[14];
    float* out = (float*)d_out;

    const int SMEM_G12 = 2 * ((128 + 256) * 272);   // 208896
    const int SMEM_TAIL = 179840;

    static bool attr_set = false;
    if (!attr_set) {
        cudaFuncSetAttribute(gemm_hmma_kernel<1>,
                             cudaFuncAttributeMaxDynamicSharedMemorySize, SMEM_G12);
        cudaFuncSetAttribute(gemm_hmma_kernel<2>,
                             cudaFuncAttributeMaxDynamicSharedMemorySize, SMEM_G12);
        cudaFuncSetAttribute(tail_kernel,
                             cudaFuncAttributeMaxDynamicSharedMemorySize, SMEM_TAIL);
        attr_set = true;
    }

    prep_x_kernel<<<MTOT / 8, 256>>>(x, Ws, bs);
    prep_w_kernel<<<(WT_TOTAL + 255) / 256, 256>>>(W1, W2, W3, Wc1);

    dim3 g1(MTOT / 128, 2);   // N=512 in two 256-wide passes
    gemm_hmma_kernel<1><<<g1, 512, SMEM_G12>>>(b1);
    gemm_hmma_kernel<2><<<MTOT / 128, 512, SMEM_G12>>>(b2);
    tail_kernel<<<MTOT / 128, 512, SMEM_TAIL>>>(b3, bc1, Wc2, bc2, Wc3, bc3, out);
}

// round 10
// speedup vs baseline: 1.0169x; 1.0169x over previous
#include <cuda_runtime.h>
#include <cuda_fp16.h>
#include <math.h>
#include <cstdint>

// ===========================================================================
// Fused MLP on HMMA fp16, gmem->smem staging via cp.async.bulk (1D TMA-style
// bulk copy + mbarrier). All GEMM operand tensors are stored in gmem as the
// EXACT padded smem tile image (128 rows x 272B, 16B row pad), so one bulk
// copy per chunk stages a whole tile ready for conflict-free ldmatrix.
//   prep_x : x fp32 -> fp16 A-blocks [512mt x 3kb]; stats proj -> g_statproj
//   prep_w : W1/W2/W3 -> fp16 B-blocks; Wc1 -> plain transposed fp16
//   gemm<1>: h1 = relu(x@W1+b1)  -> h1 A-blocks (4 kb)
//   gemm<2>: h2 = relu(h1@W2+b2) -> h2 A-blocks (2 kb)
//   tail   : gemm3 (h2@W3 -> smem comb) + C1 HMMA + C2/C3 + sigmoid
// ===========================================================================

#define MTOT 65536
#define ABLK 34816u      // 128 rows x 272B
#define BBLK2 69632u     // 256 rows x 272B

// ---------------- device scratch (block-formatted, sizes in __half) --------
__device__ __half g_x [(size_t)512 * 3 * 17408];   // x A-blocks
__device__ __half g_w1[(size_t)2 * 3 * 34816];     // W1 B-blocks (2 passes x 3 kb x 256x272B)
__device__ __half g_w2[(size_t)4 * 34816];         // W2 B-blocks (4 kb)
__device__ __half g_w3[(size_t)2 * 17408];         // W3 B-blocks (2 kb x 128x272B)
__device__ __half g_h1[(size_t)512 * 4 * 17408];   // h1 A-blocks
__device__ __half g_h2[(size_t)512 * 2 * 17408];   // h2 A-blocks
__device__ __half g_wc1t[64 * 160];
__device__ __half g_statproj[(size_t)MTOT * 32];

// ---------------- helpers --------------------------------------------------
__device__ __forceinline__ uint32_t smem_to_u32(const void* p) {
    uint32_t a;
    asm("{ .reg .u64 t; cvta.to.shared.u64 t, %1; cvt.u32.u64 %0, t; }"
        : "=r"(a) : "l"(p));
    return a;
}
__device__ __forceinline__ void ldsm4(uint32_t* r, uint32_t addr) {
    asm volatile("ldmatrix.sync.aligned.m8n8.x4.shared.b16 {%0,%1,%2,%3}, [%4];"
        : "=r"(r[0]), "=r"(r[1]), "=r"(r[2]), "=r"(r[3]) : "r"(addr));
}
__device__ __forceinline__ void mma16816(float* c, const uint32_t* a,
                                         const uint32_t* b) {
    asm volatile(
        "mma.sync.aligned.m16n8k16.row.col.f32.f16.f16.f32 "
        "{%0,%1,%2,%3}, {%4,%5,%6,%7}, {%8,%9}, {%0,%1,%2,%3};"
        : "+f"(c[0]), "+f"(c[1]), "+f"(c[2]), "+f"(c[3])
        : "r"(a[0]), "r"(a[1]), "r"(a[2]), "r"(a[3]), "r"(b[0]), "r"(b[1]));
}
__device__ __forceinline__ void cp_async16(uint32_t dst, const void* src) {
    asm volatile("cp.async.cg.shared.global [%0], [%1], 16;"
        :: "r"(dst), "l"(src));
}
#define CP_COMMIT() asm volatile("cp.async.commit_group;" ::: "memory")
#define CP_WAIT(n)  asm volatile("cp.async.wait_group %0;" :: "n"(n) : "memory")

__device__ __forceinline__ void bulk_g2s(uint32_t dst, const void* src,
                                         uint32_t bytes, uint32_t mbar) {
    asm volatile(
        "cp.async.bulk.shared::cta.global.mbarrier::complete_tx::bytes "
        "[%0], [%1], %2, [%3];"
        :: "r"(dst), "l"(src), "r"(bytes), "r"(mbar) : "memory");
}
#define MBARRIER_INIT(mbar, cnt) \
    asm volatile("mbarrier.init.shared.b64 [%0], %1;" \
        :: "r"((uint32_t)(mbar)), "r"((uint32_t)(cnt)) : "memory")
#define MBARRIER_EXPECT_TX(mbar, bytes) \
    asm volatile("mbarrier.arrive.expect_tx.shared.b64 _, [%0], %1;" \
        :: "r"((uint32_t)(mbar)), "r"((uint32_t)(bytes)) : "memory")
#define MBARRIER_WAIT_PARITY(mbar, par) do { \
    uint32_t _m = (uint32_t)(mbar); uint32_t _p = (uint32_t)(par); uint32_t _d; \
    asm volatile("{\n\t.reg .pred p;\n\t" \
        "mbarrier.try_wait.parity.acquire.cta.shared::cta.b64 p, [%1], %2;\n\t" \
        "selp.b32 %0, 1, 0, p;\n\t}" : "=r"(_d) : "r"(_m), "r"(_p) : "memory"); \
    if (!_d) { \
        asm volatile("{\n\t.reg .pred P1;\n\t" \
            "WAIT_LOOP_%=:\n\t" \
            "mbarrier.try_wait.parity.acquire.cta.shared::cta.b64 P1, [%0], %1, 0x989680;\n\t" \
            "@P1 bra.uni WAIT_DONE_%=;\n\t" \
            "bra.uni WAIT_LOOP_%=;\n\t" \
            "WAIT_DONE_%=:\n\t}" :: "r"(_m), "r"(_p) : "memory"); \
    } \
} while (0)

__device__ __forceinline__ uint32_t pack_h2(__half a, __half b) {
    __half2 t; t.x = a; t.y = b;
    return *(uint32_t*)&t;
}

// ---------------- prep_x ----------------------------------------------------
__global__ __launch_bounds__(256)
void prep_x_kernel(const float* __restrict__ x,
                   const float* __restrict__ Ws, const float* __restrict__ bs) {
    const int warp = threadIdx.x >> 5, lane = threadIdx.x & 31;
    const int r = blockIdx.x * 8 + warp;
    const float* xr = x + (size_t)r * 365;

    float v[12];
    float s = 0.f, mn = 3.4e38f, mx = -3.4e38f;
#pragma unroll
    for (int i = 0; i < 12; i++) {
        int k = lane + 32 * i;
        bool ok = k < 365;
        v[i] = ok ? xr[k] : 0.f;
        if (ok) { s += v[i]; mn = fminf(mn, v[i]); mx = fmaxf(mx, v[i]); }
    }
#pragma unroll
    for (int o = 16; o; o >>= 1) {
        s += __shfl_xor_sync(0xffffffffu, s, o);
        mn = fminf(mn, __shfl_xor_sync(0xffffffffu, mn, o));
        mx = fmaxf(mx, __shfl_xor_sync(0xffffffffu, mx, o));
    }
    const float mu = s * (1.0f / 365.0f);
    float s2 = 0.f, s3 = 0.f, s4 = 0.f;
#pragma unroll
    for (int i = 0; i < 12; i++) {
        int k = lane + 32 * i;
        if (k < 365) {
            float c = v[i] - mu, c2 = c * c;
            s2 += c2; s3 += c2 * c; s4 += c2 * c2;
        }
    }
#pragma unroll
    for (int o = 16; o; o >>= 1) {
        s2 += __shfl_xor_sync(0xffffffffu, s2, o);
        s3 += __shfl_xor_sync(0xffffffffu, s3, o);
        s4 += __shfl_xor_sync(0xffffffffu, s4, o);
    }
    const float var1 = s2 * (1.0f / 364.0f);
    const float sig = sqrtf(var1);
    const float m3 = s3 * (1.0f / 365.0f);
    const float m4 = s4 * (1.0f / 365.0f);
    const float sig2 = sig * sig;
    const float skew = m3 / (sig * sig2 + 1e-8f);
    const float kurt = m4 / (sig2 * sig2 + 1e-8f);

    {   // stats projection: lane j -> col j
        const int j = lane;
        float a = bs[j];
        a += mu   * Ws[0 * 32 + j];
        a += sig  * Ws[1 * 32 + j];
        a += mn   * Ws[2 * 32 + j];
        a += mx   * Ws[3 * 32 + j];
        a += skew * Ws[4 * 32 + j];
        a += kurt * Ws[5 * 32 + j];
        g_statproj[(size_t)r * 32 + j] = __float2half_rn(a);
    }
    // x -> A-block layout: block(mt = r>>7, kb = k>>7), 136 halves/row
    const int mt = r >> 7, rl = r & 127;
#pragma unroll
    for (int i = 0; i < 12; i++) {
        int k = lane + 32 * i;
        float val = (k < 365) ? v[i] : 0.f;
        const int kb = k >> 7, kl = k & 127;
        g_x[((size_t)(mt * 3 + kb)) * 17408 + rl * 136 + kl] = __float2half_rn(val);
    }
}

// ---------------- prep_w ----------------------------------------------------
#define W1T_ELEMS (512 * 384)
#define W2T_ELEMS (256 * 512)
#define W3T_ELEMS (128 * 256)
#define WC1T_ELEMS (64 * 160)
#define WT_TOTAL  (W1T_ELEMS + W2T_ELEMS + W3T_ELEMS + WC1T_ELEMS)

__global__ __launch_bounds__(256)
void prep_w_kernel(const float* __restrict__ W1, const float* __restrict__ W2,
                   const float* __restrict__ W3, const float* __restrict__ Wc1) {
    int idx = blockIdx.x * 256 + threadIdx.x;
    if (idx >= WT_TOTAL) return;
    if (idx < W1T_ELEMS) {
        int n = idx / 384, k = idx % 384;
        float v = (k < 365) ? W1[(size_t)k * 512 + n] : 0.f;
        int pass = n >> 8, nl = n & 255, kb = k >> 7, kl = k & 127;
        g_w1[((size_t)(pass * 3 + kb)) * 34816 + nl * 136 + kl] = __float2half_rn(v);
    } else if (idx < W1T_ELEMS + W2T_ELEMS) {
        int j = idx - W1T_ELEMS;
        int n = j / 512, k = j % 512;
        int kb = k >> 7, kl = k & 127;
        g_w2[(size_t)kb * 34816 + n * 136 + kl] = __float2half_rn(W2[(size_t)k * 256 + n]);
    } else if (idx < W1T_ELEMS + W2T_ELEMS + W3T_ELEMS) {
        int j = idx - W1T_ELEMS - W2T_ELEMS;
        int n = j / 256, k = j % 256;
        int kb = k >> 7, kl = k & 127;
        g_w3[(size_t)kb * 17408 + n * 136 + kl] = __float2half_rn(W3[(size_t)k * 128 + n]);
    } else {
        int j = idx - W1T_ELEMS - W2T_ELEMS - W3T_ELEMS;
        int n = j / 160, k = j % 160;
        g_wc1t[j] = __float2half_rn(Wc1[(size_t)k * 64 + n]);
    }
}

// ---------------- HMMA GEMM layers 1/2: bulk-copy staged, K-chunk 128 ------
template <int LAYER>
__global__ __launch_bounds__(512, 1)
void gemm_hmma_kernel(const float* __restrict__ bias) {
    constexpr int KB    = (LAYER == 1) ? 3 : 4;
    constexpr int OKB   = (LAYER == 1) ? 4 : 2;     // output chunk count
    constexpr int LDSB  = 272;
    constexpr int NWT   = 4;
    constexpr int NT    = 8;

    constexpr uint32_t A_S  = 0;
    constexpr uint32_t B_S  = ABLK;                 // 34816
    constexpr uint32_t SBUF = ABLK + BBLK2;         // 104448
    constexpr uint32_t MB   = 2 * SBUF;             // 208896

    extern __shared__ char smem[];
    const uint32_t sb = smem_to_u32(smem);

    const int tid = threadIdx.x, warp = tid >> 5, lane = tid & 31;
    const int bi = blockIdx.x;
    const int nbase = blockIdx.y * 256;
    const int wm = (warp & 3) * 32;
    const int wn = (warp >> 2) * 64;

    const char* Abase = (LAYER == 1)
        ? (const char*)g_x  + (size_t)bi * 3 * ABLK
        : (const char*)g_h1 + (size_t)bi * 4 * ABLK;
    const char* Bbase = (LAYER == 1)
        ? (const char*)g_w1 + (size_t)blockIdx.y * 3 * BBLK2
        : (const char*)g_w2;
    char* Obase = (LAYER == 1)
        ? (char*)g_h1 + (size_t)bi * 4 * ABLK
        : (char*)g_h2 + (size_t)bi * 2 * ABLK;

    if (tid == 0) {
        MBARRIER_INIT(sb + MB, 1);
        MBARRIER_INIT(sb + MB + 8, 1);
    }
    __syncthreads();
    if (tid == 0) {
        MBARRIER_EXPECT_TX(sb + MB, ABLK + BBLK2);
        bulk_g2s(sb + A_S, Abase, ABLK, sb + MB);
        bulk_g2s(sb + B_S, Bbase, BBLK2, sb + MB);
    }

    float acc[2][NT][4];
#pragma unroll
    for (int mt = 0; mt < 2; mt++)
#pragma unroll
        for (int t = 0; t < NT; t++)
#pragma unroll
            for (int j = 0; j < 4; j++) acc[mt][t][j] = 0.f;

    const uint32_t a_off = (uint32_t)(wm + (lane & 15)) * LDSB + ((lane >> 4) * 16);
    const uint32_t b_off = (uint32_t)(wn + (lane & 7) + ((lane >> 4) << 3)) * LDSB
                           + (((lane >> 3) & 1) * 16);

    for (int kb = 0; kb < KB; kb++) {
        __syncthreads();                 // all warps done with buf (kb+1)&1
        if (tid == 0 && kb + 1 < KB) {
            const uint32_t nb = sb + (uint32_t)((kb + 1) & 1) * SBUF;
            const uint32_t nm = sb + MB + ((kb + 1) & 1) * 8;
            MBARRIER_EXPECT_TX(nm, ABLK + BBLK2);
            bulk_g2s(nb + A_S, Abase + (size_t)(kb + 1) * ABLK, ABLK, nm);
            bulk_g2s(nb + B_S, Bbase + (size_t)(kb + 1) * BBLK2, BBLK2, nm);
        }
        MBARRIER_WAIT_PARITY(sb + MB + (kb & 1) * 8, (kb >> 1) & 1);

        const uint32_t bb = sb + (uint32_t)(kb & 1) * SBUF;
#pragma unroll
        for (int ks = 0; ks < 8; ks++) {
            uint32_t ah[2][4];
#pragma unroll
            for (int mt = 0; mt < 2; mt++)
                ldsm4(ah[mt], bb + A_S + a_off + mt * (16 * LDSB) + ks * 32);
#pragma unroll
            for (int t = 0; t < NWT; t++) {
                uint32_t bh[4];
                ldsm4(bh, bb + B_S + b_off + t * (16 * LDSB) + ks * 32);
#pragma unroll
                for (int mt = 0; mt < 2; mt++) {
                    mma16816(acc[mt][2 * t],     ah[mt], bh);
                    mma16816(acc[mt][2 * t + 1], ah[mt], bh + 2);
                }
            }
        }
    }

    // ---- epilogue: bias + relu -> fp16 A-block layout ----
#pragma unroll
    for (int mt = 0; mt < 2; mt++) {
        const int rl0 = wm + mt * 16 + (lane >> 2);
        const int rl1 = rl0 + 8;
#pragma unroll
        for (int t = 0; t < NT; t++) {
            const int ncol = wn + t * 8 + (lane & 3) * 2;
            const float b0 = bias[nbase + ncol];
            const float b1 = bias[nbase + ncol + 1];
            float d0 = fmaxf(acc[mt][t][0] + b0, 0.f);
            float d1 = fmaxf(acc[mt][t][1] + b1, 0.f);
            float d2 = fmaxf(acc[mt][t][2] + b0, 0.f);
            float d3 = fmaxf(acc[mt][t][3] + b1, 0.f);
            const int ncg = nbase + ncol;
            char* blk = Obase + (size_t)(ncg >> 7) * ABLK + (ncg & 127) * 2;
            *(uint32_t*)(blk + rl0 * 272) = pack_h2(__float2half_rn(d0), __float2half_rn(d1));
            *(uint32_t*)(blk + rl1 * 272) = pack_h2(__float2half_rn(d2), __float2half_rn(d3));
        }
    }
    (void)OKB;
}

// ---------------- fused tail: gemm3 (bulk-staged) + C1 HMMA + C2/C3 --------
__global__ __launch_bounds__(512, 1)
void tail_kernel(const float* __restrict__ b3,
                 const float* __restrict__ bc1,
                 const float* __restrict__ Wc2, const float* __restrict__ bc2,
                 const float* __restrict__ Wc3, const float* __restrict__ bc3,
                 float* __restrict__ out) {
    constexpr int LDSB = 272;
    constexpr uint32_t A_S   = 0;        // 34816
    constexpr uint32_t B_ALL = 34816;    // both W3 blocks: 69632
    constexpr int LDH = 336;
    constexpr uint32_t COMB = 104448;    // 128 x 336 = 43008
    constexpr uint32_t WC1  = COMB + 43008;   // 21504 -> 147456
    constexpr uint32_t C1S  = WC1 + 21504;    // 33280 -> 168960
    constexpr uint32_t WC2S = C1S + 33280;    // 8192  -> 202240
    constexpr uint32_t WC3S = WC2S + 8192;    // 128   -> 210432
    constexpr uint32_t MB   = 210560;         // 16    -> total 210576

    extern __shared__ char smem[];
    const uint32_t sb = smem_to_u32(smem);
    float* smf = (float*)smem;

    const int tid = threadIdx.x, warp = tid >> 5, lane = tid & 31;
    const int bi = blockIdx.x;
    const int row0 = bi * 128;
    const int wm = (warp & 3) * 32;
    const int wn3 = (warp >> 2) * 32;

    if (tid == 0) {
        MBARRIER_INIT(sb + MB, 1);
        MBARRIER_INIT(sb + MB + 8, 1);
    }

    // regular cp.async for head constants + statproj
    for (int i = tid; i < 1280; i += 512) {
        int r = i / 20, g = i % 20;
        cp_async16(sb + WC1 + r * LDH + g * 16, g_wc1t + r * 160 + g * 8);
    }
    {
        const int r = tid >> 2, g = tid & 3;    // 512 granules
        cp_async16(sb + COMB + r * LDH + 256 + g * 16,
                   g_statproj + (size_t)(row0 + r) * 32 + g * 8);
    }
    if (tid < 512) cp_async16(sb + WC2S + tid * 16, Wc2 + tid * 4);
    if (tid < 8)   cp_async16(sb + WC3S + tid * 16, Wc3 + tid * 4);
    CP_COMMIT();
    __syncthreads();

    const char* Abase = (const char*)g_h2 + (size_t)bi * 2 * ABLK;
    if (tid == 0) {
        MBARRIER_EXPECT_TX(sb + MB, ABLK + 2 * ABLK);
        bulk_g2s(sb + A_S, Abase, ABLK, sb + MB);
        bulk_g2s(sb + B_ALL, (const char*)g_w3, 2 * ABLK, sb + MB);
    }

    float acc[2][4][4];
#pragma unroll
    for (int mt = 0; mt < 2; mt++)
#pragma unroll
        for (int t = 0; t < 4; t++)
#pragma unroll
            for (int j = 0; j < 4; j++) acc[mt][t][j] = 0.f;

    const uint32_t a_off = (uint32_t)(wm + (lane & 15)) * LDSB + ((lane >> 4) * 16);
    const uint32_t b_off3 = (uint32_t)(wn3 + (lane & 7) + ((lane >> 4) << 3)) * LDSB
                            + (((lane >> 3) & 1) * 16);

    for (int kb = 0; kb < 2; kb++) {
        MBARRIER_WAIT_PARITY(sb + MB + kb * 8, 0);
        const uint32_t Bb = sb + B_ALL + kb * ABLK;
#pragma unroll
        for (int ks = 0; ks < 8; ks++) {
            uint32_t ah[2][4];
#pragma unroll
            for (int mt = 0; mt < 2; mt++)
                ldsm4(ah[mt], sb + A_S + a_off + mt * (16 * LDSB) + ks * 32);
#pragma unroll
            for (int t = 0; t < 2; t++) {
                uint32_t bh[4];
                ldsm4(bh, Bb + b_off3 + t * (16 * LDSB) + ks * 32);
#pragma unroll
                for (int mt = 0; mt < 2; mt++) {
                    mma16816(acc[mt][2 * t],     ah[mt], bh);
                    mma16816(acc[mt][2 * t + 1], ah[mt], bh + 2);
                }
            }
        }
        if (kb == 0) {
            __syncthreads();          // all done reading A buffer
            if (tid == 0) {
                MBARRIER_EXPECT_TX(sb + MB + 8, ABLK);
                bulk_g2s(sb + A_S, Abase + ABLK, ABLK, sb + MB + 8);
            }
        }
    }

    // gemm3 epilogue: bias+relu -> smem comb cols [0,128)
    __half* combh = (__half*)(smem + COMB);
#pragma unroll
    for (int mt = 0; mt < 2; mt++) {
        const int r0 = wm + mt * 16 + (lane >> 2);
        const int r1 = r0 + 8;
#pragma unroll
        for (int t = 0; t < 4; t++) {
            const int ncol = wn3 + t * 8 + (lane & 3) * 2;
            const float b0 = b3[ncol], b1 = b3[ncol + 1];
            float d0 = fmaxf(acc[mt][t][0] + b0, 0.f);
            float d1 = fmaxf(acc[mt][t][1] + b1, 0.f);
            float d2 = fmaxf(acc[mt][t][2] + b0, 0.f);
            float d3 = fmaxf(acc[mt][t][3] + b1, 0.f);
            *(uint32_t*)((char*)combh + r0 * LDH + ncol * 2) =
                pack_h2(__float2half_rn(d0), __float2half_rn(d1));
            *(uint32_t*)((char*)combh + r1 * LDH + ncol * 2) =
                pack_h2(__float2half_rn(d2), __float2half_rn(d3));
        }
    }
    CP_WAIT(0);
    __syncthreads();

    // ---- C1: HMMA comb[128,160] @ Wc1T[64,160]; warp grid 4m x 4n ----
    const int wnh = (warp >> 2) * 16;
    float acch[2][2][4];
#pragma unroll
    for (int mt = 0; mt < 2; mt++)
#pragma unroll
        for (int t = 0; t < 2; t++)
#pragma unroll
            for (int j = 0; j < 4; j++) acch[mt][t][j] = 0.f;

    const uint32_t a_offh = (uint32_t)(wm + (lane & 15)) * LDH + ((lane >> 4) * 16);
    const uint32_t b_offh = (uint32_t)(wnh + (lane & 7) + ((lane >> 4) << 3)) * LDH
                            + (((lane >> 3) & 1) * 16);
#pragma unroll
    for (int ks = 0; ks < 10; ks++) {
        uint32_t ah[2][4];
#pragma unroll
        for (int mt = 0; mt < 2; mt++)
            ldsm4(ah[mt], sb + COMB + a_offh + mt * (16 * LDH) + ks * 32);
        uint32_t bh[4];
        ldsm4(bh, sb + WC1 + b_offh + ks * 32);
#pragma unroll
        for (int mt = 0; mt < 2; mt++) {
            mma16816(acch[mt][0], ah[mt], bh);
            mma16816(acch[mt][1], ah[mt], bh + 2);
        }
    }
    float* c1s = smf + C1S / 4;
#pragma unroll
    for (int mt = 0; mt < 2; mt++) {
        const int r0 = wm + mt * 16 + (lane >> 2);
        const int r1 = r0 + 8;
#pragma unroll
        for (int t = 0; t < 2; t++) {
            const int ncol = wnh + t * 8 + (lane & 3) * 2;
            const float b0 = bc1[ncol], b1 = bc1[ncol + 1];
            c1s[r0 * 65 + ncol]     = fmaxf(acch[mt][t][0] + b0, 0.f);
            c1s[r0 * 65 + ncol + 1] = fmaxf(acch[mt][t][1] + b1, 0.f);
            c1s[r1 * 65 + ncol]     = fmaxf(acch[mt][t][2] + b0, 0.f);
            c1s[r1 * 65 + ncol + 1] = fmaxf(acch[mt][t][3] + b1, 0.f);
        }
    }
    __syncthreads();

    // ---- C2: [128,64]@[64,32] fp32 ----
    float* wc2s = smf + WC2S / 4;
    float* c2s  = smf + COMB / 4;            // reuse comb region, stride 33
    {
        const int r = tid >> 2;
        const int j0 = (tid & 3) * 8;
        float a[8];
#pragma unroll
        for (int j = 0; j < 8; j++) a[j] = bc2[j0 + j];
        const float* c1r = c1s + r * 65;
        for (int k = 0; k < 64; k++) {
            const float v = c1r[k];
            const float* w = wc2s + k * 32 + j0;
#pragma unroll
            for (int j = 0; j < 8; j++) a[j] += v * w[j];
        }
        float* c2r = c2s + r * 33;
#pragma unroll
        for (int j = 0; j < 8; j++) c2r[j0 + j] = fmaxf(a[j], 0.f);
    }
    __syncthreads();

    // ---- C3 + sigmoid ----
    if (tid < 128) {
        const float* c2r = c2s + tid * 33;
        const float* w3 = smf + WC3S / 4;
        float z = bc3[0];
#pragma unroll
        for (int k = 0; k < 32; k++) z += c2r[k] * w3[k];
        out[row0 + tid] = 1.0f / (1.0f + expf(-z));
    }
}

// ---------------- launch ---------------------------------------------------
extern "C" void kernel_launch(void* const* d_in, const int* in_sizes, int n_in,
                              void* d_out, int out_size) {
    const float* x   = (const float*)d_in[0];
    const float* W1  = (const float*)d_in[1];
    const float* b1  = (const float*)d_in[2];
    const float* W2  = (const float*)d_in[3];
    const float* b2  = (const float*)d_in[4];
    const float* W3  = (const float*)d_in[5];
    const float* b3  = (const float*)d_in[6];
    const float* Ws  = (const float*)d_in[7];
    const float* bs  = (const float*)d_in[8];
    const float* Wc1 = (const float*)d_in[9];
    const float* bc1 = (const float*)d_in[10];
    const float* Wc2 = (const float*)d_in[11];
    const float* bc2 = (const float*)d_in[12];
    const float* Wc3 = (const float*)d_in[13];
    const float* bc3 = (const float*)d_in[14];
    float* out = (float*)d_out;

    const int SMEM_G12 = 2 * 104448 + 32;   // 208928
    const int SMEM_TAIL = 210592;

    static bool attr_set = false;
    if (!attr_set) {
        cudaFuncSetAttribute(gemm_hmma_kernel<1>,
                             cudaFuncAttributeMaxDynamicSharedMemorySize, SMEM_G12);
        cudaFuncSetAttribute(gemm_hmma_kernel<2>,
                             cudaFuncAttributeMaxDynamicSharedMemorySize, SMEM_G12);
        cudaFuncSetAttribute(tail_kernel,
                             cudaFuncAttributeMaxDynamicSharedMemorySize, SMEM_TAIL);
        attr_set = true;
    }

    prep_x_kernel<<<MTOT / 8, 256>>>(x, Ws, bs);
    prep_w_kernel<<<(WT_TOTAL + 255) / 256, 256>>>(W1, W2, W3, Wc1);

    dim3 g1(MTOT / 128, 2);   // N=512 in two 256-wide passes
    gemm_hmma_kernel<1><<<g1, 512, SMEM_G12>>>(b1);
    gemm_hmma_kernel<2><<<MTOT / 128, 512, SMEM_G12>>>(b2);
    tail_kernel<<<MTOT / 128, 512, SMEM_TAIL>>>(b3, bc1, Wc2, bc2, Wc3, bc3, out);
}

// round 11
// speedup vs baseline: 1.0882x; 1.0700x over previous
#include <cuda_runtime.h>
#include <cuda_fp16.h>
#include <math.h>
#include <cstdint>

// ===========================================================================
// Fused MLP on HMMA fp16, bulk-copy staged (cp.async.bulk + mbarrier), GEMM
// operands stored in gmem as exact padded smem tile images (row = 272B).
// Round 11: 256-thr CTAs, 64x64 warp tiles (8 ldsm / 32 mma per k16).
//   prep_x : x fp32 -> fp16 A-blocks; stats proj -> g_statproj
//   prep_w : W1/W2/W3 -> fp16 B-blocks; Wc1 -> transposed fp16
//   gemm<1>: h1 = relu(x@W1+b1)  -> A-blocks
//   gemm<2>: h2 = relu(h1@W2+b2) -> A-blocks
//   tail   : gemm3 (h2@W3 -> smem comb) + C1 HMMA + C2/C3 + sigmoid
// ===========================================================================

#define MTOT 65536
#define ABLK 34816u      // 128 rows x 272B
#define BBLK2 69632u     // 256 rows x 272B

// ---------------- device scratch -------------------------------------------
__device__ __half g_x [(size_t)512 * 3 * 17408];
__device__ __half g_w1[(size_t)2 * 3 * 34816];
__device__ __half g_w2[(size_t)4 * 34816];
__device__ __half g_w3[(size_t)2 * 17408];
__device__ __half g_h1[(size_t)512 * 4 * 17408];
__device__ __half g_h2[(size_t)512 * 2 * 17408];
__device__ __half g_wc1t[64 * 160];
__device__ __half g_statproj[(size_t)MTOT * 32];

// ---------------- helpers --------------------------------------------------
__device__ __forceinline__ uint32_t smem_to_u32(const void* p) {
    uint32_t a;
    asm("{ .reg .u64 t; cvta.to.shared.u64 t, %1; cvt.u32.u64 %0, t; }"
        : "=r"(a) : "l"(p));
    return a;
}
__device__ __forceinline__ void ldsm4(uint32_t* r, uint32_t addr) {
    asm volatile("ldmatrix.sync.aligned.m8n8.x4.shared.b16 {%0,%1,%2,%3}, [%4];"
        : "=r"(r[0]), "=r"(r[1]), "=r"(r[2]), "=r"(r[3]) : "r"(addr));
}
__device__ __forceinline__ void mma16816(float* c, const uint32_t* a,
                                         const uint32_t* b) {
    asm volatile(
        "mma.sync.aligned.m16n8k16.row.col.f32.f16.f16.f32 "
        "{%0,%1,%2,%3}, {%4,%5,%6,%7}, {%8,%9}, {%0,%1,%2,%3};"
        : "+f"(c[0]), "+f"(c[1]), "+f"(c[2]), "+f"(c[3])
        : "r"(a[0]), "r"(a[1]), "r"(a[2]), "r"(a[3]), "r"(b[0]), "r"(b[1]));
}
__device__ __forceinline__ void cp_async16(uint32_t dst, const void* src) {
    asm volatile("cp.async.cg.shared.global [%0], [%1], 16;"
        :: "r"(dst), "l"(src));
}
#define CP_COMMIT() asm volatile("cp.async.commit_group;" ::: "memory")
#define CP_WAIT(n)  asm volatile("cp.async.wait_group %0;" :: "n"(n) : "memory")

__device__ __forceinline__ void bulk_g2s(uint32_t dst, const void* src,
                                         uint32_t bytes, uint32_t mbar) {
    asm volatile(
        "cp.async.bulk.shared::cta.global.mbarrier::complete_tx::bytes "
        "[%0], [%1], %2, [%3];"
        :: "r"(dst), "l"(src), "r"(bytes), "r"(mbar) : "memory");
}
#define MBARRIER_INIT(mbar, cnt) \
    asm volatile("mbarrier.init.shared.b64 [%0], %1;" \
        :: "r"((uint32_t)(mbar)), "r"((uint32_t)(cnt)) : "memory")
#define MBARRIER_EXPECT_TX(mbar, bytes) \
    asm volatile("mbarrier.arrive.expect_tx.shared.b64 _, [%0], %1;" \
        :: "r"((uint32_t)(mbar)), "r"((uint32_t)(bytes)) : "memory")
#define MBARRIER_WAIT_PARITY(mbar, par) do { \
    uint32_t _m = (uint32_t)(mbar); uint32_t _p = (uint32_t)(par); uint32_t _d; \
    asm volatile("{\n\t.reg .pred p;\n\t" \
        "mbarrier.try_wait.parity.acquire.cta.shared::cta.b64 p, [%1], %2;\n\t" \
        "selp.b32 %0, 1, 0, p;\n\t}" : "=r"(_d) : "r"(_m), "r"(_p) : "memory"); \
    if (!_d) { \
        asm volatile("{\n\t.reg .pred P1;\n\t" \
            "WAIT_LOOP_%=:\n\t" \
            "mbarrier.try_wait.parity.acquire.cta.shared::cta.b64 P1, [%0], %1, 0x989680;\n\t" \
            "@P1 bra.uni WAIT_DONE_%=;\n\t" \
            "bra.uni WAIT_LOOP_%=;\n\t" \
            "WAIT_DONE_%=:\n\t}" :: "r"(_m), "r"(_p) : "memory"); \
    } \
} while (0)

__device__ __forceinline__ uint32_t pack_h2(__half a, __half b) {
    __half2 t; t.x = a; t.y = b;
    return *(uint32_t*)&t;
}

// ---------------- prep_x ----------------------------------------------------
__global__ __launch_bounds__(256)
void prep_x_kernel(const float* __restrict__ x,
                   const float* __restrict__ Ws, const float* __restrict__ bs) {
    const int warp = threadIdx.x >> 5, lane = threadIdx.x & 31;
    const int r = blockIdx.x * 8 + warp;
    const float* xr = x + (size_t)r * 365;

    float v[12];
    float s = 0.f, mn = 3.4e38f, mx = -3.4e38f;
#pragma unroll
    for (int i = 0; i < 12; i++) {
        int k = lane + 32 * i;
        bool ok = k < 365;
        v[i] = ok ? xr[k] : 0.f;
        if (ok) { s += v[i]; mn = fminf(mn, v[i]); mx = fmaxf(mx, v[i]); }
    }
#pragma unroll
    for (int o = 16; o; o >>= 1) {
        s += __shfl_xor_sync(0xffffffffu, s, o);
        mn = fminf(mn, __shfl_xor_sync(0xffffffffu, mn, o));
        mx = fmaxf(mx, __shfl_xor_sync(0xffffffffu, mx, o));
    }
    const float mu = s * (1.0f / 365.0f);
    float s2 = 0.f, s3 = 0.f, s4 = 0.f;
#pragma unroll
    for (int i = 0; i < 12; i++) {
        int k = lane + 32 * i;
        if (k < 365) {
            float c = v[i] - mu, c2 = c * c;
            s2 += c2; s3 += c2 * c; s4 += c2 * c2;
        }
    }
#pragma unroll
    for (int o = 16; o; o >>= 1) {
        s2 += __shfl_xor_sync(0xffffffffu, s2, o);
        s3 += __shfl_xor_sync(0xffffffffu, s3, o);
        s4 += __shfl_xor_sync(0xffffffffu, s4, o);
    }
    const float var1 = s2 * (1.0f / 364.0f);
    const float sig = sqrtf(var1);
    const float m3 = s3 * (1.0f / 365.0f);
    const float m4 = s4 * (1.0f / 365.0f);
    const float sig2 = sig * sig;
    const float skew = m3 / (sig * sig2 + 1e-8f);
    const float kurt = m4 / (sig2 * sig2 + 1e-8f);

    {
        const int j = lane;
        float a = bs[j];
        a += mu   * Ws[0 * 32 + j];
        a += sig  * Ws[1 * 32 + j];
        a += mn   * Ws[2 * 32 + j];
        a += mx   * Ws[3 * 32 + j];
        a += skew * Ws[4 * 32 + j];
        a += kurt * Ws[5 * 32 + j];
        g_statproj[(size_t)r * 32 + j] = __float2half_rn(a);
    }
    const int mt = r >> 7, rl = r & 127;
#pragma unroll
    for (int i = 0; i < 12; i++) {
        int k = lane + 32 * i;
        float val = (k < 365) ? v[i] : 0.f;
        const int kb = k >> 7, kl = k & 127;
        g_x[((size_t)(mt * 3 + kb)) * 17408 + rl * 136 + kl] = __float2half_rn(val);
    }
}

// ---------------- prep_w ----------------------------------------------------
#define W1T_ELEMS (512 * 384)
#define W2T_ELEMS (256 * 512)
#define W3T_ELEMS (128 * 256)
#define WC1T_ELEMS (64 * 160)
#define WT_TOTAL  (W1T_ELEMS + W2T_ELEMS + W3T_ELEMS + WC1T_ELEMS)

__global__ __launch_bounds__(256)
void prep_w_kernel(const float* __restrict__ W1, const float* __restrict__ W2,
                   const float* __restrict__ W3, const float* __restrict__ Wc1) {
    int idx = blockIdx.x * 256 + threadIdx.x;
    if (idx >= WT_TOTAL) return;
    if (idx < W1T_ELEMS) {
        int n = idx / 384, k = idx % 384;
        float v = (k < 365) ? W1[(size_t)k * 512 + n] : 0.f;
        int pass = n >> 8, nl = n & 255, kb = k >> 7, kl = k & 127;
        g_w1[((size_t)(pass * 3 + kb)) * 34816 + nl * 136 + kl] = __float2half_rn(v);
    } else if (idx < W1T_ELEMS + W2T_ELEMS) {
        int j = idx - W1T_ELEMS;
        int n = j / 512, k = j % 512;
        int kb = k >> 7, kl = k & 127;
        g_w2[(size_t)kb * 34816 + n * 136 + kl] = __float2half_rn(W2[(size_t)k * 256 + n]);
    } else if (idx < W1T_ELEMS + W2T_ELEMS + W3T_ELEMS) {
        int j = idx - W1T_ELEMS - W2T_ELEMS;
        int n = j / 256, k = j % 256;
        int kb = k >> 7, kl = k & 127;
        g_w3[(size_t)kb * 17408 + n * 136 + kl] = __float2half_rn(W3[(size_t)k * 128 + n]);
    } else {
        int j = idx - W1T_ELEMS - W2T_ELEMS - W3T_ELEMS;
        int n = j / 160, k = j % 160;
        g_wc1t[j] = __float2half_rn(Wc1[(size_t)k * 64 + n]);
    }
}

// ---------------- HMMA GEMM layers 1/2: 256 thr, 64x64 warp tiles ----------
template <int LAYER>
__global__ __launch_bounds__(256, 1)
void gemm_hmma_kernel(const float* __restrict__ bias) {
    constexpr int KB    = (LAYER == 1) ? 3 : 4;
    constexpr int LDSB  = 272;

    constexpr uint32_t A_S  = 0;
    constexpr uint32_t B_S  = ABLK;
    constexpr uint32_t SBUF = ABLK + BBLK2;         // 104448
    constexpr uint32_t MB   = 2 * SBUF;             // 208896

    extern __shared__ char smem[];
    const uint32_t sb = smem_to_u32(smem);

    const int tid = threadIdx.x, warp = tid >> 5, lane = tid & 31;
    const int bi = blockIdx.x;
    const int nbase = blockIdx.y * 256;
    const int wm = (warp & 1) * 64;        // 2 M halves of 64 rows
    const int wn = (warp >> 1) * 64;       // 4 N quarters of 64 cols

    const char* Abase = (LAYER == 1)
        ? (const char*)g_x  + (size_t)bi * 3 * ABLK
        : (const char*)g_h1 + (size_t)bi * 4 * ABLK;
    const char* Bbase = (LAYER == 1)
        ? (const char*)g_w1 + (size_t)blockIdx.y * 3 * BBLK2
        : (const char*)g_w2;
    char* Obase = (LAYER == 1)
        ? (char*)g_h1 + (size_t)bi * 4 * ABLK
        : (char*)g_h2 + (size_t)bi * 2 * ABLK;

    if (tid == 0) {
        MBARRIER_INIT(sb + MB, 1);
        MBARRIER_INIT(sb + MB + 8, 1);
    }
    __syncthreads();
    if (tid == 0) {
        MBARRIER_EXPECT_TX(sb + MB, ABLK + BBLK2);
        bulk_g2s(sb + A_S, Abase, ABLK, sb + MB);
        bulk_g2s(sb + B_S, Bbase, BBLK2, sb + MB);
    }

    float acc[4][8][4];                     // 4 m16 x 8 n8 x 4 = 128 regs
#pragma unroll
    for (int mt = 0; mt < 4; mt++)
#pragma unroll
        for (int t = 0; t < 8; t++)
#pragma unroll
            for (int j = 0; j < 4; j++) acc[mt][t][j] = 0.f;

    const uint32_t a_off = (uint32_t)(wm + (lane & 15)) * LDSB + ((lane >> 4) * 16);
    const uint32_t b_off = (uint32_t)(wn + (lane & 7) + ((lane >> 4) << 3)) * LDSB
                           + (((lane >> 3) & 1) * 16);

    for (int kb = 0; kb < KB; kb++) {
        __syncthreads();                    // buf (kb+1)&1 free for overwrite
        if (tid == 0 && kb + 1 < KB) {
            const uint32_t nb = sb + (uint32_t)((kb + 1) & 1) * SBUF;
            const uint32_t nm = sb + MB + ((kb + 1) & 1) * 8;
            MBARRIER_EXPECT_TX(nm, ABLK + BBLK2);
            bulk_g2s(nb + A_S, Abase + (size_t)(kb + 1) * ABLK, ABLK, nm);
            bulk_g2s(nb + B_S, Bbase + (size_t)(kb + 1) * BBLK2, BBLK2, nm);
        }
        MBARRIER_WAIT_PARITY(sb + MB + (kb & 1) * 8, (kb >> 1) & 1);

        const uint32_t bb = sb + (uint32_t)(kb & 1) * SBUF;
#pragma unroll
        for (int ks = 0; ks < 8; ks++) {
            uint32_t ah[4][4];
#pragma unroll
            for (int mt = 0; mt < 4; mt++)
                ldsm4(ah[mt], bb + A_S + a_off + mt * (16 * LDSB) + ks * 32);
#pragma unroll
            for (int t = 0; t < 4; t++) {
                uint32_t bh[4];
                ldsm4(bh, bb + B_S + b_off + t * (16 * LDSB) + ks * 32);
#pragma unroll
                for (int mt = 0; mt < 4; mt++) {
                    mma16816(acc[mt][2 * t],     ah[mt], bh);
                    mma16816(acc[mt][2 * t + 1], ah[mt], bh + 2);
                }
            }
        }
    }

    // ---- epilogue: bias + relu -> fp16 A-block layout ----
#pragma unroll
    for (int mt = 0; mt < 4; mt++) {
        const int rl0 = wm + mt * 16 + (lane >> 2);
        const int rl1 = rl0 + 8;
#pragma unroll
        for (int t = 0; t < 8; t++) {
            const int ncol = wn + t * 8 + (lane & 3) * 2;
            const float b0 = bias[nbase + ncol];
            const float b1 = bias[nbase + ncol + 1];
            float d0 = fmaxf(acc[mt][t][0] + b0, 0.f);
            float d1 = fmaxf(acc[mt][t][1] + b1, 0.f);
            float d2 = fmaxf(acc[mt][t][2] + b0, 0.f);
            float d3 = fmaxf(acc[mt][t][3] + b1, 0.f);
            const int ncg = nbase + ncol;
            char* blk = Obase + (size_t)(ncg >> 7) * ABLK + (ncg & 127) * 2;
            *(uint32_t*)(blk + rl0 * 272) = pack_h2(__float2half_rn(d0), __float2half_rn(d1));
            *(uint32_t*)(blk + rl1 * 272) = pack_h2(__float2half_rn(d2), __float2half_rn(d3));
        }
    }
}

// ---------------- fused tail: 256 thr ---------------------------------------
__global__ __launch_bounds__(256, 1)
void tail_kernel(const float* __restrict__ b3,
                 const float* __restrict__ bc1,
                 const float* __restrict__ Wc2, const float* __restrict__ bc2,
                 const float* __restrict__ Wc3, const float* __restrict__ bc3,
                 float* __restrict__ out) {
    constexpr int LDSB = 272;
    constexpr uint32_t A_S   = 0;
    constexpr uint32_t B_ALL = 34816;
    constexpr int LDH = 336;
    constexpr uint32_t COMB = 104448;
    constexpr uint32_t WC1  = COMB + 43008;
    constexpr uint32_t C1S  = WC1 + 21504;
    constexpr uint32_t WC2S = C1S + 33280;
    constexpr uint32_t WC3S = WC2S + 8192;
    constexpr uint32_t MB   = 210560;

    extern __shared__ char smem[];
    const uint32_t sb = smem_to_u32(smem);
    float* smf = (float*)smem;

    const int tid = threadIdx.x, warp = tid >> 5, lane = tid & 31;
    const int bi = blockIdx.x;
    const int row0 = bi * 128;
    const int wm = (warp & 1) * 64;        // 2 M halves
    const int wn3 = (warp >> 1) * 64;      // gemm3: N=128?? -> see below

    if (tid == 0) {
        MBARRIER_INIT(sb + MB, 1);
        MBARRIER_INIT(sb + MB + 8, 1);
    }

    // head constants + statproj via cp.async
    for (int i = tid; i < 1280; i += 256) {
        int r = i / 20, g = i % 20;
        cp_async16(sb + WC1 + r * LDH + g * 16, g_wc1t + r * 160 + g * 8);
    }
    for (int i = tid; i < 512; i += 256) {
        const int r = i >> 2, g = i & 3;
        cp_async16(sb + COMB + r * LDH + 256 + g * 16,
                   g_statproj + (size_t)(row0 + r) * 32 + g * 8);
    }
    for (int i = tid; i < 512; i += 256)
        cp_async16(sb + WC2S + i * 16, Wc2 + i * 4);
    if (tid < 8) cp_async16(sb + WC3S + tid * 16, Wc3 + tid * 4);
    CP_COMMIT();
    __syncthreads();

    const char* Abase = (const char*)g_h2 + (size_t)bi * 2 * ABLK;
    if (tid == 0) {
        MBARRIER_EXPECT_TX(sb + MB, ABLK + 2 * ABLK);
        bulk_g2s(sb + A_S, Abase, ABLK, sb + MB);
        bulk_g2s(sb + B_ALL, (const char*)g_w3, 2 * ABLK, sb + MB);
    }

    // gemm3: M=128, N=128 with 8 warps -> warp grid 2m x 2n of 64x64.
    // wn3 for N: (warp>>1) in 0..3 but N=128 has only 2 quarters of 64 ->
    // use (warp>>1)&1 for n, and split K... simpler: warp grid 2m x 2n and
    // each (m,n) pair duplicated across 2 warps splitting the k16 loop? No —
    // keep 2m x 2n = 4 groups, 2 warps each splitting ks range.
    const int wn3b = ((warp >> 1) & 1) * 64;
    const int kshalf = (warp >> 2);        // 0 or 1: which half of ks range

    float acc[4][8][4];
#pragma unroll
    for (int mt = 0; mt < 4; mt++)
#pragma unroll
        for (int t = 0; t < 8; t++)
#pragma unroll
            for (int j = 0; j < 4; j++) acc[mt][t][j] = 0.f;

    const uint32_t a_off = (uint32_t)(wm + (lane & 15)) * LDSB + ((lane >> 4) * 16);
    const uint32_t b_off3 = (uint32_t)(wn3b + (lane & 7) + ((lane >> 4) << 3)) * LDSB
                            + (((lane >> 3) & 1) * 16);

    for (int kb = 0; kb < 2; kb++) {
        MBARRIER_WAIT_PARITY(sb + MB + kb * 8, 0);
        const uint32_t Bb = sb + B_ALL + kb * ABLK;
        // each warp handles 4 of the 8 ks steps (k-split across warp pairs)
#pragma unroll
        for (int ks4 = 0; ks4 < 4; ks4++) {
            const int ks = kshalf * 4 + ks4;
            uint32_t ah[4][4];
#pragma unroll
            for (int mt = 0; mt < 4; mt++)
                ldsm4(ah[mt], sb + A_S + a_off + mt * (16 * LDSB) + ks * 32);
#pragma unroll
            for (int t = 0; t < 4; t++) {
                uint32_t bh[4];
                ldsm4(bh, Bb + b_off3 + t * (16 * LDSB) + ks * 32);
#pragma unroll
                for (int mt = 0; mt < 4; mt++) {
                    mma16816(acc[mt][2 * t],     ah[mt], bh);
                    mma16816(acc[mt][2 * t + 1], ah[mt], bh + 2);
                }
            }
        }
        if (kb == 0) {
            __syncthreads();
            if (tid == 0) {
                MBARRIER_EXPECT_TX(sb + MB + 8, ABLK);
                bulk_g2s(sb + A_S, Abase + ABLK, ABLK, sb + MB + 8);
            }
        }
    }

    // gemm3 epilogue: k-split partial sums -> combine via smem.
    // Warp pairs (w, w+4) hold partials for the same 64x64 tile.
    // Lower warps (0-3) write partials to c1s scratch, upper warps add.
    float* part = smf + C1S / 4;           // reuse c1s region as scratch (8320 fl)
    // each lower warp stores its 128 values per... too big; instead do
    // sequential: lower warps store all 128 acc values to scratch region
    // (4 warps x 32 lanes x 128 vals = 16384 fl = 64KB > region). Use comb
    // region trick instead: atomically accumulate via two passes.
    // Pass 1: warps 0-3 write fp32 partials into COMB..(COMB+128*336) as raw
    // fp32? comb rows are 336B; need 128x128 fp32 = 64KB; COMB region is
    // only 43008B. Use A_S pipeline region (104448B free now): stride 129.
    {
        float* pa = smf + 0;               // pipeline region as fp32 scratch
        __syncthreads();                   // gemm3 reads of smem A done
        if (warp < 4) {
#pragma unroll
            for (int mt = 0; mt < 4; mt++) {
                const int r0 = wm + mt * 16 + (lane >> 2);
                const int r1 = r0 + 8;
#pragma unroll
                for (int t = 0; t < 8; t++) {
                    const int ncol = wn3b + t * 8 + (lane & 3) * 2;
                    pa[r0 * 129 + ncol]     = acc[mt][t][0];
                    pa[r0 * 129 + ncol + 1] = acc[mt][t][1];
                    pa[r1 * 129 + ncol]     = acc[mt][t][2];
                    pa[r1 * 129 + ncol + 1] = acc[mt][t][3];
                }
            }
        }
        __syncthreads();
        __half* combh = (__half*)(smem + COMB);
        if (warp >= 4) {
#pragma unroll
            for (int mt = 0; mt < 4; mt++) {
                const int r0 = wm + mt * 16 + (lane >> 2);
                const int r1 = r0 + 8;
#pragma unroll
                for (int t = 0; t < 8; t++) {
                    const int ncol = wn3b + t * 8 + (lane & 3) * 2;
                    const float b0 = b3[ncol], b1 = b3[ncol + 1];
                    float d0 = fmaxf(acc[mt][t][0] + pa[r0 * 129 + ncol]     + b0, 0.f);
                    float d1 = fmaxf(acc[mt][t][1] + pa[r0 * 129 + ncol + 1] + b1, 0.f);
                    float d2 = fmaxf(acc[mt][t][2] + pa[r1 * 129 + ncol]     + b0, 0.f);
                    float d3 = fmaxf(acc[mt][t][3] + pa[r1 * 129 + ncol + 1] + b1, 0.f);
                    *(uint32_t*)((char*)combh + r0 * LDH + ncol * 2) =
                        pack_h2(__float2half_rn(d0), __float2half_rn(d1));
                    *(uint32_t*)((char*)combh + r1 * LDH + ncol * 2) =
                        pack_h2(__float2half_rn(d2), __float2half_rn(d3));
                }
            }
        }
    }
    CP_WAIT(0);
    __syncthreads();

    // ---- C1: HMMA comb[128,160] @ Wc1T[64,160]; warp grid 2m x 4n ----
    const int wmh = (warp & 1) * 64;
    const int wnh = (warp >> 1) * 16;
    float acch[4][2][4];
#pragma unroll
    for (int mt = 0; mt < 4; mt++)
#pragma unroll
        for (int t = 0; t < 2; t++)
#pragma unroll
            for (int j = 0; j < 4; j++) acch[mt][t][j] = 0.f;

    const uint32_t a_offh = (uint32_t)(wmh + (lane & 15)) * LDH + ((lane >> 4) * 16);
    const uint32_t b_offh = (uint32_t)(wnh + (lane & 7) + ((lane >> 4) << 3)) * LDH
                            + (((lane >> 3) & 1) * 16);
#pragma unroll
    for (int ks = 0; ks < 10; ks++) {
        uint32_t ah[4][4];
#pragma unroll
        for (int mt = 0; mt < 4; mt++)
            ldsm4(ah[mt], sb + COMB + a_offh + mt * (16 * LDH) + ks * 32);
        uint32_t bh[4];
        ldsm4(bh, sb + WC1 + b_offh + ks * 32);
#pragma unroll
        for (int mt = 0; mt < 4; mt++) {
            mma16816(acch[mt][0], ah[mt], bh);
            mma16816(acch[mt][1], ah[mt], bh + 2);
        }
    }
    float* c1s = smf + C1S / 4;
#pragma unroll
    for (int mt = 0; mt < 4; mt++) {
        const int r0 = wmh + mt * 16 + (lane >> 2);
        const int r1 = r0 + 8;
#pragma unroll
        for (int t = 0; t < 2; t++) {
            const int ncol = wnh + t * 8 + (lane & 3) * 2;
            const float b0 = bc1[ncol], b1 = bc1[ncol + 1];
            c1s[r0 * 65 + ncol]     = fmaxf(acch[mt][t][0] + b0, 0.f);
            c1s[r0 * 65 + ncol + 1] = fmaxf(acch[mt][t][1] + b1, 0.f);
            c1s[r1 * 65 + ncol]     = fmaxf(acch[mt][t][2] + b0, 0.f);
            c1s[r1 * 65 + ncol + 1] = fmaxf(acch[mt][t][3] + b1, 0.f);
        }
    }
    __syncthreads();

    // ---- C2: [128,64]@[64,32] fp32 ----
    float* wc2s = smf + WC2S / 4;
    float* c2s  = smf + COMB / 4;            // stride 33
    {
        const int r = tid >> 1;
        const int j0 = (tid & 1) * 16;
        float a[16];
#pragma unroll
        for (int j = 0; j < 16; j++) a[j] = bc2[j0 + j];
        const float* c1r = c1s + r * 65;
        for (int k = 0; k < 64; k++) {
            const float v = c1r[k];
            const float* w = wc2s + k * 32 + j0;
#pragma unroll
            for (int j = 0; j < 16; j++) a[j] += v * w[j];
        }
        float* c2r = c2s + r * 33;
#pragma unroll
        for (int j = 0; j < 16; j++) c2r[j0 + j] = fmaxf(a[j], 0.f);
    }
    __syncthreads();

    // ---- C3 + sigmoid ----
    if (tid < 128) {
        const float* c2r = c2s + tid * 33;
        const float* w3 = smf + WC3S / 4;
        float z = bc3[0];
#pragma unroll
        for (int k = 0; k < 32; k++) z += c2r[k] * w3[k];
        out[row0 + tid] = 1.0f / (1.0f + expf(-z));
    }
}

// ---------------- launch ---------------------------------------------------
extern "C" void kernel_launch(void* const* d_in, const int* in_sizes, int n_in,
                              void* d_out, int out_size) {
    const float* x   = (const float*)d_in[0];
    const float* W1  = (const float*)d_in[1];
    const float* b1  = (const float*)d_in[2];
    const float* W2  = (const float*)d_in[3];
    const float* b2  = (const float*)d_in[4];
    const float* W3  = (const float*)d_in[5];
    const float* b3  = (const float*)d_in[6];
    const float* Ws  = (const float*)d_in[7];
    const float* bs  = (const float*)d_in[8];
    const float* Wc1 = (const float*)d_in[9];
    const float* bc1 = (const float*)d_in[10];
    const float* Wc2 = (const float*)d_in[11];
    const float* bc2 = (const float*)d_in[12];
    const float* Wc3 = (const float*)d_in[13];
    const float* bc3 = (const float*)d_in[14];
    float* out = (float*)d_out;

    const int SMEM_G12 = 2 * 104448 + 32;   // 208928
    const int SMEM_TAIL = 210592;

    static bool attr_set = false;
    if (!attr_set) {
        cudaFuncSetAttribute(gemm_hmma_kernel<1>,
                             cudaFuncAttributeMaxDynamicSharedMemorySize, SMEM_G12);
        cudaFuncSetAttribute(gemm_hmma_kernel<2>,
                             cudaFuncAttributeMaxDynamicSharedMemorySize, SMEM_G12);
        cudaFuncSetAttribute(tail_kernel,
                             cudaFuncAttributeMaxDynamicSharedMemorySize, SMEM_TAIL);
        attr_set = true;
    }

    prep_x_kernel<<<MTOT / 8, 256>>>(x, Ws, bs);
    prep_w_kernel<<<(WT_TOTAL + 255) / 256, 256>>>(W1, W2, W3, Wc1);

    dim3 g1(MTOT / 128, 2);
    gemm_hmma_kernel<1><<<g1, 256, SMEM_G12>>>(b1);
    gemm_hmma_kernel<2><<<MTOT / 128, 256, SMEM_G12>>>(b2);
    tail_kernel<<<MTOT / 128, 256, SMEM_TAIL>>>(b3, bc1, Wc2, bc2, Wc3, bc3, out);
}